// round 5
// baseline (speedup 1.0000x reference)
#include <cuda_runtime.h>
#include <cstdint>

#define T_ 4
#define B_ 16
#define NN 1024
#define C_ 256
#define CH_ 1024
#define SC (B_*C_*NN)      // 4194304 elements per t (bytes for int8 tensors)
#define SCH (B_*CH_*NN)

// ---------------- scratch ----------------
__device__ int8_t g_xsT[(size_t)T_*SC];
__device__ int8_t g_qT [(size_t)T_*SC];
__device__ int8_t g_kT [(size_t)T_*SC];
__device__ int8_t g_y0T[(size_t)T_*SC];
__device__ int8_t g_z0T[(size_t)T_*SC];
__device__ int8_t g_z1T[(size_t)T_*SCH];
__device__ float  g_x1 [(size_t)T_*SC];
__device__ int8_t g_pq [256*768];
__device__ int8_t g_pk [256*768];
__device__ int8_t g_pp [256*768];
__device__ int8_t g_pw1[1024*768];
__device__ int8_t g_pw2[256*3072];
__device__ float  g_sq[256], g_sk[256], g_sp[256], g_sw1[1024], g_sw2[256];

// ---------------- helpers ----------------
__device__ __forceinline__ uint32_t smem_u32(const void* p) {
    uint32_t a;
    asm("{ .reg .u64 t; cvta.to.shared.u64 t, %1; cvt.u32.u64 %0, t; }" : "=r"(a) : "l"(p));
    return a;
}
__device__ __forceinline__ void cpasync16(uint32_t dst, const void* src) {
    asm volatile("cp.async.cg.shared.global [%0], [%1], 16;" :: "r"(dst), "l"(src) : "memory");
}
__device__ __forceinline__ void cp_commit() { asm volatile("cp.async.commit_group;" ::: "memory"); }
template<int N> __device__ __forceinline__ void cp_wait() {
    asm volatile("cp.async.wait_group %0;" :: "n"(N) : "memory");
}
__device__ __forceinline__ void ldsm4(uint32_t& r0, uint32_t& r1, uint32_t& r2, uint32_t& r3, uint32_t addr) {
    asm volatile("ldmatrix.sync.aligned.m8n8.x4.shared.b16 {%0,%1,%2,%3}, [%4];"
                 : "=r"(r0), "=r"(r1), "=r"(r2), "=r"(r3) : "r"(addr));
}
__device__ __forceinline__ void mma_s8(int* d, const uint32_t* a, uint32_t b0, uint32_t b1) {
    asm volatile("mma.sync.aligned.m16n8k32.row.col.s32.s8.s8.s32 "
                 "{%0,%1,%2,%3}, {%4,%5,%6,%7}, {%8,%9}, {%0,%1,%2,%3};"
                 : "+r"(d[0]), "+r"(d[1]), "+r"(d[2]), "+r"(d[3])
                 : "r"(a[0]), "r"(a[1]), "r"(a[2]), "r"(a[3]), "r"(b0), "r"(b1));
}
__device__ __forceinline__ int dp4a(int a, int b, int c) {
    int d; asm("dp4a.s32.s32 %0, %1, %2, %3;" : "=r"(d) : "r"(a), "r"(b), "r"(c)); return d;
}

// ---------------- weight prep: row max, then 3-digit int8 split ----------------
__global__ void rowmax_kernel(const float* __restrict__ W, float* __restrict__ sig, int M, int K) {
    int row = blockIdx.x * 8 + (threadIdx.x >> 5);
    if (row >= M) return;
    int lane = threadIdx.x & 31;
    float mx = 0.f;
    for (int k = lane; k < K; k += 32) mx = fmaxf(mx, fabsf(W[(size_t)row * K + k]));
#pragma unroll
    for (int o = 16; o; o >>= 1) mx = fmaxf(mx, __shfl_xor_sync(0xFFFFFFFFu, mx, o));
    if (lane == 0) sig[row] = (mx > 0.f) ? mx / 127.0f : 1.0f;
}

__global__ void pack3_kernel(const float* __restrict__ W, const float* __restrict__ sig,
                             int8_t* __restrict__ P, int M, int K) {
    int i = blockIdx.x * 256 + threadIdx.x;
    if (i >= M * K) return;
    int m = i / K, k = i % K;
    int NKC = K >> 7;
    float s = sig[m];
    float w = W[i];
    float a1 = rintf(w / s);
    float r = fmaf(-a1, s, w);
    float s2 = s * (1.0f / 254.0f);
    float a2 = rintf(r / s2);
    r = fmaf(-a2, s2, r);
    float s3 = s2 * (1.0f / 254.0f);
    float a3 = rintf(r / s3);
    int bm = m >> 7, rin = m & 127, kc = k >> 7, c = k & 127;
    uint32_t byte = (uint32_t)(rin * 128 + c);
    byte ^= (byte >> 3) & 0x70;
    size_t blk0 = ((size_t)(bm * 3 + 0) * NKC + kc) * 16384 + byte;
    size_t step = (size_t)NKC * 16384;
    P[blk0]            = (int8_t)(int)a1;
    P[blk0 + step]     = (int8_t)(int)a2;
    P[blk0 + 2 * step] = (int8_t)(int)a3;
}

// ---------------- LIF + transpose: fp32 [t,b,c,n] -> int8 spikes [t,b,n,c] ----------------
__global__ void lif_t_kernel(const float* __restrict__ in, int8_t* __restrict__ out, int Cdim) {
    __shared__ int8_t st[4][32][80];   // row stride 80B: multiple of 16 for uint4 reads
    int n0 = blockIdx.x * 32, c0 = blockIdx.y * 64, b = blockIdx.z;
    int nl = threadIdx.x & 31, cg = threadIdx.x >> 5;
#pragma unroll
    for (int pass = 0; pass < 8; pass++) {
        int cl = pass * 8 + cg;
        int c = c0 + cl;
        float mem = 0.f;
#pragma unroll
        for (int t = 0; t < T_; t++) {
            float v = mem * 0.5f + in[((size_t)(t * B_ + b) * Cdim + c) * NN + n0 + nl];
            float sp = (v >= 1.0f) ? 1.f : 0.f;
            st[t][nl][cl] = (int8_t)(sp != 0.f);
            mem = v * (1.f - sp);
        }
    }
    __syncthreads();
    int rr = threadIdx.x >> 1, hf = threadIdx.x & 1;
    int t = rr >> 5, n = rr & 31;
    size_t row = ((size_t)(t * B_ + b) * NN + n0 + n) * Cdim + c0 + hf * 32;
    uint4* d = (uint4*)(out + row);
    const uint4* s = (const uint4*)(&st[t][n][hf * 32]);
    d[0] = s[0]; d[1] = s[1];
}

// ---------------- attention (int8 transposed layout) ----------------
__global__ void attn_kernel(const int8_t* __restrict__ q, const int8_t* __restrict__ k,
                            int8_t* __restrict__ y, const float* __restrict__ alpha_p) {
    int idx = blockIdx.x * 256 + threadIdx.x;
    int h = idx & 7;
    int n = (idx >> 3) & 1023;
    int b = idx >> 13;
    float alpha = *alpha_p;
    size_t basep = ((size_t)(b * NN + n)) * C_ + h * 32;

    float qs[T_];
#pragma unroll
    for (int t = 0; t < T_; t++) {
        const uint4* p = (const uint4*)(q + (size_t)t * SC + basep);
        uint4 v0 = p[0], v1 = p[1];
        int s = 0;
        s = dp4a((int)v0.x, 0x01010101, s); s = dp4a((int)v0.y, 0x01010101, s);
        s = dp4a((int)v0.z, 0x01010101, s); s = dp4a((int)v0.w, 0x01010101, s);
        s = dp4a((int)v1.x, 0x01010101, s); s = dp4a((int)v1.y, 0x01010101, s);
        s = dp4a((int)v1.z, 0x01010101, s); s = dp4a((int)v1.w, 0x01010101, s);
        qs[t] = (float)s;
    }
    float ms[T_];
    ms[0] = qs[0];
#pragma unroll
    for (int t = 1; t < T_; t++) ms[t] = alpha * ms[t - 1] + (1.f - alpha) * qs[t - 1];

    float mem = 0.f;
#pragma unroll
    for (int t = 0; t < T_; t++) {
        float v = mem * 0.5f + (ms[t] + qs[t]);
        float sp = (v >= 0.5f) ? 1.f : 0.f;
        mem = v * (1.f - sp);
        const uint4* kp = (const uint4*)(k + (size_t)t * SC + basep);
        uint4* yp = (uint4*)(y + (size_t)t * SC + basep);
        if (sp != 0.f) { yp[0] = kp[0]; yp[1] = kp[1]; }
        else { uint4 z = {0, 0, 0, 0}; yp[0] = z; yp[1] = z; }
    }
}

// ---------------- int8 IMMA GEMM with fused epilogues ----------------
// CTA 128(M) x 128(N), chunk K=128 int8, 3-stage cp.async pipeline.
// Weights = 3 int8 digits (scales sigma * 254^-tau), term-major accumulation.
// EPI 0: bn affine + LIF -> int8 spikes transposed [t,b,n,m]
// EPI 1: (d+bias)*scale+shift + res -> fp32 [t,b,m,n]
// EPI 2: EPI1 write + LIF on result -> spikes (proj layer: x1 and z0 fused)
#define OF_STG  98304
#define OF_MEMV (98304 + 18432)
#define SMEM_SP (98304 + 18432 + 65536 + 1024)
#define SMEM_NF (98304 + 1024)

template<int CSRC, int COUT, int EPI>
__global__ __launch_bounds__(256) void gemm_i8(
    const int8_t* __restrict__ pack, const int8_t* __restrict__ XT,
    const float* __restrict__ sig,
    float* __restrict__ outF, int8_t* __restrict__ outS,
    const float* __restrict__ bias1, const float* __restrict__ scale,
    const float* __restrict__ shift, const float* __restrict__ res, float thr)
{
    extern __shared__ char smraw[];
    uint32_t smb0 = smem_u32(smraw);
    uint32_t smb = (smb0 + 1023u) & ~1023u;
    char* base = smraw + (smb - smb0);

    const int NKC = CSRC / 128;       // K-chunks per term
    const int CHT = 3 * NKC;          // chunks per timestep
    const int G = 4 * CHT;
    const int n0g = blockIdx.x * 128;
    const int m0g = blockIdx.y * 128;
    const int b = blockIdx.z;
    const int tid = threadIdx.x;
    const int wid = tid >> 5, lane = tid & 31;
    const int mw = (wid >> 2) * 64, nw = (wid & 3) * 32;
    const int r = lane >> 2, qn = lane & 3;

    float psig[4][2];
#pragma unroll
    for (int mi = 0; mi < 4; mi++)
#pragma unroll
        for (int h = 0; h < 2; h++)
            psig[mi][h] = sig[m0g + mw + mi * 16 + r + h * 8];

    int accs[4][4][4];
    float accf[4][4][4];
#pragma unroll
    for (int mi = 0; mi < 4; mi++)
#pragma unroll
        for (int j = 0; j < 4; j++)
#pragma unroll
            for (int e = 0; e < 4; e++) { accs[mi][j][e] = 0; accf[mi][j][e] = 0.f; }

    float* memvp = (float*)(base + OF_MEMV);
    char* stg = base + OF_STG;

    auto issue = [&](int g) {
        int t = g / CHT, rem = g % CHT;
        int tau = rem / NKC, kc = rem % NKC;
        int buf = g % 3;
        // A: linear copy of pre-swizzled 16KB digit block
        const int8_t* asrc = pack + ((size_t)(blockIdx.y * 3 + tau) * NKC + kc) * 16384 + tid * 64;
        uint32_t adst = smb + buf * 32768 + tid * 64;
#pragma unroll
        for (int i = 0; i < 4; i++) cpasync16(adst + i * 16, asrc + i * 16);
        // B: 128 rows x 128B int8, swizzled dst
        int row = tid >> 1, hf = tid & 1;
        const int8_t* bsrc = XT + ((size_t)((t * B_ + b) * NN + n0g + row)) * CSRC + kc * 128 + hf * 64;
        uint32_t bb = smb + buf * 32768 + 16384;
#pragma unroll
        for (int i = 0; i < 4; i++) {
            uint32_t byte = (uint32_t)(row * 128 + hf * 64 + i * 16);
            byte ^= (byte >> 3) & 0x70;
            cpasync16(bb + byte, bsrc + i * 16);
        }
        cp_commit();
    };

    issue(0); issue(1);
    for (int g = 0; g < G; g++) {
        cp_wait<1>();
        __syncthreads();
        if (g + 2 < G) issue(g + 2);

        uint32_t aB = smb + (g % 3) * 32768;
        uint32_t bB = aB + 16384;
#pragma unroll
        for (int ks = 0; ks < 4; ks++) {
            int kb = ks * 32 + (lane >> 4) * 16;
            uint32_t af[4][4], bf[2][4];
#pragma unroll
            for (int mi = 0; mi < 4; mi++) {
                uint32_t byte = (uint32_t)((mw + mi * 16 + (lane & 15)) * 128 + kb);
                byte ^= (byte >> 3) & 0x70;
                ldsm4(af[mi][0], af[mi][1], af[mi][2], af[mi][3], aB + byte);
            }
#pragma unroll
            for (int j2 = 0; j2 < 2; j2++) {
                uint32_t byte = (uint32_t)((nw + j2 * 16 + (lane & 15)) * 128 + kb);
                byte ^= (byte >> 3) & 0x70;
                ldsm4(bf[j2][0], bf[j2][1], bf[j2][2], bf[j2][3], bB + byte);
            }
#pragma unroll
            for (int mi = 0; mi < 4; mi++)
#pragma unroll
                for (int j = 0; j < 4; j++)
                    mma_s8(accs[mi][j], af[mi], bf[j >> 1][j & 1], bf[j >> 1][(j & 1) + 2]);
        }

        int rem = g % CHT;
        if (rem % NKC == NKC - 1) {
            int tau = rem / NKC;
            float c = (tau == 0) ? 1.f : ((tau == 1) ? (1.f / 254.f) : (1.f / 64516.f));
#pragma unroll
            for (int mi = 0; mi < 4; mi++)
#pragma unroll
                for (int h = 0; h < 2; h++) {
                    float fac = psig[mi][h] * c;
#pragma unroll
                    for (int j = 0; j < 4; j++)
#pragma unroll
                        for (int eo = 0; eo < 2; eo++) {
                            int e = h * 2 + eo;
                            accf[mi][j][e] += (float)accs[mi][j][e] * fac;
                            accs[mi][j][e] = 0;
                        }
                }
        }

        if (rem == CHT - 1) {
            int t = g / CHT;
            // ---- epilogue ----
#pragma unroll
            for (int mi = 0; mi < 4; mi++)
#pragma unroll
                for (int h = 0; h < 2; h++) {
                    int ml = mw + mi * 16 + r + h * 8;
                    int m = m0g + ml;
                    float pb = bias1 ? bias1[m] : 0.f;
                    float sc = scale[m], sh = shift[m];
#pragma unroll
                    for (int j = 0; j < 4; j++) {
                        int nl = nw + j * 8 + qn * 2;
                        float v0 = (accf[mi][j][h * 2 + 0] + pb) * sc + sh;
                        float v1 = (accf[mi][j][h * 2 + 1] + pb) * sc + sh;
                        accf[mi][j][h * 2 + 0] = 0.f;
                        accf[mi][j][h * 2 + 1] = 0.f;
                        if (EPI >= 1) {
                            size_t o = ((size_t)((t * B_ + b) * COUT) + m) * NN + n0g + nl;
                            float2 rv = *(const float2*)&res[o];
                            v0 += rv.x; v1 += rv.y;
                            float2 ov = {v0, v1};
                            *(float2*)&outF[o] = ov;
                        }
                        if (EPI != 1) {
                            float m0v = (t == 0) ? 0.f : memvp[nl * 128 + ml];
                            float m1v = (t == 0) ? 0.f : memvp[(nl + 1) * 128 + ml];
                            float u0 = m0v * 0.5f + v0;
                            float u1 = m1v * 0.5f + v1;
                            float sp0 = (u0 >= thr) ? 1.f : 0.f;
                            float sp1 = (u1 >= thr) ? 1.f : 0.f;
                            memvp[nl * 128 + ml] = u0 * (1.f - sp0);
                            memvp[(nl + 1) * 128 + ml] = u1 * (1.f - sp1);
                            stg[nl * 144 + ml] = (char)(sp0 != 0.f);
                            stg[(nl + 1) * 144 + ml] = (char)(sp1 != 0.f);
                        }
                    }
                }
            if (EPI != 1) {
                __syncthreads();
                int rowi = tid >> 1, hf2 = tid & 1;
                const uint4* s4 = (const uint4*)(stg + rowi * 144 + hf2 * 64);
                uint4* d4 = (uint4*)(outS + ((size_t)((t * B_ + b) * NN + n0g + rowi)) * COUT
                                           + m0g + hf2 * 64);
                d4[0] = s4[0]; d4[1] = s4[1]; d4[2] = s4[2]; d4[3] = s4[3];
            }
        }
    }
}

// ---------------- launch ----------------
extern "C" void kernel_launch(void* const* d_in, const int* in_sizes, int n_in,
                              void* d_out, int out_size) {
    const float* x         = (const float*)d_in[0];
    const float* q_w       = (const float*)d_in[1];
    const float* q_g       = (const float*)d_in[2];
    const float* q_b       = (const float*)d_in[3];
    const float* k_w       = (const float*)d_in[4];
    const float* k_g       = (const float*)d_in[5];
    const float* k_b       = (const float*)d_in[6];
    const float* proj_w    = (const float*)d_in[7];
    const float* proj_bias = (const float*)d_in[8];
    const float* proj_g    = (const float*)d_in[9];
    const float* proj_b2   = (const float*)d_in[10];
    const float* mem_alpha = (const float*)d_in[11];
    const float* w1        = (const float*)d_in[12];
    const float* b1        = (const float*)d_in[13];
    const float* bn1_g     = (const float*)d_in[14];
    const float* bn1_b     = (const float*)d_in[15];
    const float* w2        = (const float*)d_in[16];
    const float* b2        = (const float*)d_in[17];
    const float* bn2_g     = (const float*)d_in[18];
    const float* bn2_b     = (const float*)d_in[19];
    float* out = (float*)d_out;

    int8_t *xsT, *qT, *kT, *y0T, *z0T, *z1T, *pq, *pk, *pp, *pw1, *pw2;
    float *x1, *sq, *sk, *sp, *sw1, *sw2;
    cudaGetSymbolAddress((void**)&xsT, g_xsT);
    cudaGetSymbolAddress((void**)&qT,  g_qT);
    cudaGetSymbolAddress((void**)&kT,  g_kT);
    cudaGetSymbolAddress((void**)&y0T, g_y0T);
    cudaGetSymbolAddress((void**)&z0T, g_z0T);
    cudaGetSymbolAddress((void**)&z1T, g_z1T);
    cudaGetSymbolAddress((void**)&x1,  g_x1);
    cudaGetSymbolAddress((void**)&pq,  g_pq);
    cudaGetSymbolAddress((void**)&pk,  g_pk);
    cudaGetSymbolAddress((void**)&pp,  g_pp);
    cudaGetSymbolAddress((void**)&pw1, g_pw1);
    cudaGetSymbolAddress((void**)&pw2, g_pw2);
    cudaGetSymbolAddress((void**)&sq,  g_sq);
    cudaGetSymbolAddress((void**)&sk,  g_sk);
    cudaGetSymbolAddress((void**)&sp,  g_sp);
    cudaGetSymbolAddress((void**)&sw1, g_sw1);
    cudaGetSymbolAddress((void**)&sw2, g_sw2);

    cudaFuncSetAttribute(gemm_i8<256, 256, 0>,  cudaFuncAttributeMaxDynamicSharedMemorySize, SMEM_SP);
    cudaFuncSetAttribute(gemm_i8<256, 1024, 0>, cudaFuncAttributeMaxDynamicSharedMemorySize, SMEM_SP);
    cudaFuncSetAttribute(gemm_i8<256, 256, 2>,  cudaFuncAttributeMaxDynamicSharedMemorySize, SMEM_SP);
    cudaFuncSetAttribute(gemm_i8<1024, 256, 1>, cudaFuncAttributeMaxDynamicSharedMemorySize, SMEM_NF);

    // weight prep
    rowmax_kernel<<<32, 256>>>(q_w, sq, 256, 256);
    rowmax_kernel<<<32, 256>>>(k_w, sk, 256, 256);
    rowmax_kernel<<<32, 256>>>(proj_w, sp, 256, 256);
    rowmax_kernel<<<128, 256>>>(w1, sw1, 1024, 256);
    rowmax_kernel<<<32, 256>>>(w2, sw2, 256, 1024);
    pack3_kernel<<<256, 256>>>(q_w, sq, pq, 256, 256);
    pack3_kernel<<<256, 256>>>(k_w, sk, pk, 256, 256);
    pack3_kernel<<<256, 256>>>(proj_w, sp, pp, 256, 256);
    pack3_kernel<<<1024, 256>>>(w1, sw1, pw1, 1024, 256);
    pack3_kernel<<<1024, 256>>>(w2, sw2, pw2, 256, 1024);

    dim3 lifg(32, 4, 16);
    dim3 gC(8, 2, 16);
    dim3 gH(8, 8, 16);

    // 1. xsT = lifT(x)
    lif_t_kernel<<<lifg, 256>>>(x, xsT, C_);
    // 2/3. q,k: GEMM + bn + LIF -> transposed int8 spikes
    gemm_i8<256, 256, 0><<<gC, 256, SMEM_SP>>>(pq, xsT, sq, nullptr, qT, nullptr, q_g, q_b, nullptr, 1.f);
    gemm_i8<256, 256, 0><<<gC, 256, SMEM_SP>>>(pk, xsT, sk, nullptr, kT, nullptr, k_g, k_b, nullptr, 1.f);
    // 4. attention
    attn_kernel<<<(B_ * NN * 8) / 256, 256>>>(qT, kT, y0T, mem_alpha);
    // 5. x1 = x + bn(proj @ y0 + bias); z0 = lif(x1)  (fully fused)
    gemm_i8<256, 256, 2><<<gC, 256, SMEM_SP>>>(pp, y0T, sp, x1, z0T, proj_bias, proj_g, proj_b2, x, 1.f);
    // 6. z1 = lif(bn1(w1 @ z0 + b1))  (fused)
    gemm_i8<256, 1024, 0><<<gH, 256, SMEM_SP>>>(pw1, z0T, sw1, nullptr, z1T, b1, bn1_g, bn1_b, nullptr, 1.f);
    // 7. out = x1 + bn2(w2 @ z1 + b2)
    gemm_i8<1024, 256, 1><<<gC, 256, SMEM_NF>>>(pw2, z1T, sw2, out, nullptr, b2, bn2_g, bn2_b, x1, 0.f);
}

// round 7
// speedup vs baseline: 1.1456x; 1.1456x over previous
#include <cuda_runtime.h>
#include <cstdint>

#define T_ 4
#define B_ 16
#define NN 1024
#define C_ 256
#define CH_ 1024
#define SC (B_*C_*NN)       // 4194304 int8 elems per t
#define SQK (B_*NN*512)     // merged q|k per t
#define SCH (B_*CH_*NN)

// ---------------- scratch ----------------
__device__ int8_t g_xsT [(size_t)T_*SC];
__device__ int8_t g_qkT [(size_t)T_*SQK];   // [t][b][n][512]: cols 0-255 q, 256-511 k
__device__ int8_t g_y0T [(size_t)T_*SC];
__device__ int8_t g_z0T [(size_t)T_*SC];
__device__ int8_t g_z1T [(size_t)T_*SCH];
__device__ float  g_x1  [(size_t)T_*SC];
__device__ int8_t g_pqk [512*768];
__device__ int8_t g_pp  [256*768];
__device__ int8_t g_pw1 [1024*768];
__device__ int8_t g_pw2 [256*3072];
__device__ float  g_sqk[512], g_spj[256], g_sw1[1024], g_sw2[256];

// ---------------- helpers ----------------
__device__ __forceinline__ uint32_t smem_u32(const void* p) {
    uint32_t a;
    asm("{ .reg .u64 t; cvta.to.shared.u64 t, %1; cvt.u32.u64 %0, t; }" : "=r"(a) : "l"(p));
    return a;
}
__device__ __forceinline__ void cpasync16(uint32_t dst, const void* src) {
    asm volatile("cp.async.cg.shared.global [%0], [%1], 16;" :: "r"(dst), "l"(src) : "memory");
}
__device__ __forceinline__ void cp_commit() { asm volatile("cp.async.commit_group;" ::: "memory"); }
template<int N> __device__ __forceinline__ void cp_wait() {
    asm volatile("cp.async.wait_group %0;" :: "n"(N) : "memory");
}
__device__ __forceinline__ void ldsm4(uint32_t& r0, uint32_t& r1, uint32_t& r2, uint32_t& r3, uint32_t addr) {
    asm volatile("ldmatrix.sync.aligned.m8n8.x4.shared.b16 {%0,%1,%2,%3}, [%4];"
                 : "=r"(r0), "=r"(r1), "=r"(r2), "=r"(r3) : "r"(addr));
}
// A = s8 weight digits, B = u8 activations ({0,1} or {0,254})
__device__ __forceinline__ void mma_s8u8(int* d, const uint32_t* a, uint32_t b0, uint32_t b1) {
    asm volatile("mma.sync.aligned.m16n8k32.row.col.s32.s8.u8.s32 "
                 "{%0,%1,%2,%3}, {%4,%5,%6,%7}, {%8,%9}, {%0,%1,%2,%3};"
                 : "+r"(d[0]), "+r"(d[1]), "+r"(d[2]), "+r"(d[3])
                 : "r"(a[0]), "r"(a[1]), "r"(a[2]), "r"(a[3]), "r"(b0), "r"(b1));
}
__device__ __forceinline__ int dp4a(int a, int b, int c) {
    int d; asm("dp4a.s32.s32 %0, %1, %2, %3;" : "=r"(d) : "r"(a), "r"(b), "r"(c)); return d;
}

// ---------------- weight prep (2 launches total) ----------------
__global__ void rowmax_all(const float* __restrict__ qw, const float* __restrict__ kw,
                           const float* __restrict__ pw, const float* __restrict__ w1,
                           const float* __restrict__ w2) {
    int rid = blockIdx.x * 8 + (threadIdx.x >> 5);
    int lane = threadIdx.x & 31;
    const float* src; int K; float* dst; int row;
    if (rid < 512)       { src = (rid < 256) ? qw + (size_t)rid*256 : kw + (size_t)(rid-256)*256;
                           K = 256; dst = g_sqk + rid; }
    else if (rid < 768)  { row = rid - 512;  src = pw + (size_t)row*256;  K = 256;  dst = g_spj + row; }
    else if (rid < 1792) { row = rid - 768;  src = w1 + (size_t)row*256;  K = 256;  dst = g_sw1 + row; }
    else                 { row = rid - 1792; src = w2 + (size_t)row*1024; K = 1024; dst = g_sw2 + row; }
    float mx = 0.f;
    for (int k = lane; k < K; k += 32) mx = fmaxf(mx, fabsf(src[k]));
#pragma unroll
    for (int o = 16; o; o >>= 1) mx = fmaxf(mx, __shfl_xor_sync(0xFFFFFFFFu, mx, o));
    if (lane == 0) *dst = (mx > 0.f) ? mx / 127.0f : 1.0f;
}

__device__ __forceinline__ void pack_one(float w, float s, int8_t* dst, int m, int k, int NKC) {
    float a1 = rintf(w / s);
    float r = fmaf(-a1, s, w);
    float s2 = s * (1.0f / 254.0f);
    float a2 = rintf(r / s2);
    r = fmaf(-a2, s2, r);
    float s3 = s2 * (1.0f / 254.0f);
    float a3 = rintf(r / s3);
    int bm = m >> 7, rin = m & 127, kc = k >> 7, c = k & 127;
    uint32_t byte = (uint32_t)(rin * 128 + c);
    byte ^= (byte >> 3) & 0x70;
    size_t blk0 = ((size_t)(bm * 3 + 0) * NKC + kc) * 16384 + byte;
    size_t step = (size_t)NKC * 16384;
    dst[blk0]            = (int8_t)(int)a1;
    dst[blk0 + step]     = (int8_t)(int)a2;
    dst[blk0 + 2 * step] = (int8_t)(int)a3;
}

__global__ void pack_all(const float* __restrict__ qw, const float* __restrict__ kw,
                         const float* __restrict__ pw, const float* __restrict__ w1,
                         const float* __restrict__ w2) {
    int idx = blockIdx.x * 256 + threadIdx.x;
    if (idx < 131072) {                       // merged qk: M=512, K=256
        int m = idx >> 8, k = idx & 255;
        float w = (m < 256) ? qw[m * 256 + k] : kw[(m - 256) * 256 + k];
        pack_one(w, g_sqk[m], g_pqk, m, k, 2);
    } else if (idx < 196608) {                // proj: 256x256
        int i = idx - 131072; int m = i >> 8, k = i & 255;
        pack_one(pw[i], g_spj[m], g_pp, m, k, 2);
    } else if (idx < 458752) {                // w1: 1024x256
        int i = idx - 196608; int m = i >> 8, k = i & 255;
        pack_one(w1[i], g_sw1[m], g_pw1, m, k, 2);
    } else if (idx < 720896) {                // w2: 256x1024
        int i = idx - 458752; int m = i >> 10, k = i & 1023;
        pack_one(w2[i], g_sw2[m], g_pw2, m, k, 8);
    }
}

// ---------------- LIF + transpose: fp32 [t,b,c,n] -> int8 spikes [t,b,n,c] ----------------
__global__ void lif_t_kernel(const float* __restrict__ in, int8_t* __restrict__ out) {
    __shared__ int8_t st[4][32][80];
    int n0 = blockIdx.x * 32, c0 = blockIdx.y * 64, b = blockIdx.z;
    int nl = threadIdx.x & 31, cg = threadIdx.x >> 5;
#pragma unroll
    for (int pass = 0; pass < 8; pass++) {
        int cl = pass * 8 + cg;
        int c = c0 + cl;
        float mem = 0.f;
#pragma unroll
        for (int t = 0; t < T_; t++) {
            float v = mem * 0.5f + in[((size_t)(t * B_ + b) * C_ + c) * NN + n0 + nl];
            float sp = (v >= 1.0f) ? 1.f : 0.f;
            st[t][nl][cl] = (int8_t)(sp != 0.f);
            mem = v * (1.f - sp);
        }
    }
    __syncthreads();
    int rr = threadIdx.x >> 1, hf = threadIdx.x & 1;
    int t = rr >> 5, n = rr & 31;
    size_t row = ((size_t)(t * B_ + b) * NN + n0 + n) * C_ + c0 + hf * 32;
    uint4* d = (uint4*)(out + row);
    const uint4* s = (const uint4*)(&st[t][n][hf * 32]);
    d[0] = s[0]; d[1] = s[1];
}

// ---------------- attention (reads merged qkT) ----------------
__global__ void attn_kernel(const int8_t* __restrict__ qk, int8_t* __restrict__ y,
                            const float* __restrict__ alpha_p) {
    int idx = blockIdx.x * 256 + threadIdx.x;
    int h = idx & 7;
    int n = (idx >> 3) & 1023;
    int b = idx >> 13;
    float alpha = *alpha_p;
    size_t baseq = ((size_t)(b * NN + n)) * 512 + h * 32;
    size_t basey = ((size_t)(b * NN + n)) * C_ + h * 32;

    float qs[T_];
#pragma unroll
    for (int t = 0; t < T_; t++) {
        const uint4* p = (const uint4*)(qk + (size_t)t * SQK + baseq);
        uint4 v0 = p[0], v1 = p[1];
        int s = 0;
        s = dp4a((int)v0.x, 0x01010101, s); s = dp4a((int)v0.y, 0x01010101, s);
        s = dp4a((int)v0.z, 0x01010101, s); s = dp4a((int)v0.w, 0x01010101, s);
        s = dp4a((int)v1.x, 0x01010101, s); s = dp4a((int)v1.y, 0x01010101, s);
        s = dp4a((int)v1.z, 0x01010101, s); s = dp4a((int)v1.w, 0x01010101, s);
        qs[t] = (float)s;
    }
    float ms[T_];
    ms[0] = qs[0];
#pragma unroll
    for (int t = 1; t < T_; t++) ms[t] = alpha * ms[t - 1] + (1.f - alpha) * qs[t - 1];

    float mem = 0.f;
#pragma unroll
    for (int t = 0; t < T_; t++) {
        float v = mem * 0.5f + (ms[t] + qs[t]);
        float sp = (v >= 0.5f) ? 1.f : 0.f;
        mem = v * (1.f - sp);
        const uint4* kp = (const uint4*)(qk + (size_t)t * SQK + baseq + 256);
        uint4* yp = (uint4*)(y + (size_t)t * SC + basey);
        if (sp != 0.f) { yp[0] = kp[0]; yp[1] = kp[1]; }
        else { uint4 z = {0, 0, 0, 0}; yp[0] = z; yp[1] = z; }
    }
}

// ---------------- int8 IMMA GEMM ----------------
// CTA 128(M) x 64(N); 8 warps 4m x 2n; warp 32x32; chunk K=128 int8.
// Digit terms: tau0 -> hi accumulator (act {0,1}); tau1 (act {0,254}) and tau2
// ({0,1}) -> lo accumulator. value = sigma * (hi + lo/254^2), all exact in s32.
// Pipeline: cp_wait<0> -> __syncthreads -> issue(g+1) -> MMA(g).
// (issue AFTER the barrier: slot (g+1)&1 was last read in iter g-1, ordered.)
// EPI 0: bn affine + LIF -> int8 spikes transposed [t,b,n,m]
// EPI 1: (v+bias)*scale+shift + res -> fp32 [t,b,m,n]
// EPI 2: EPI1 + LIF(result) -> spikes (proj: x1 and z0 fused)
#define OF_B01  32768
#define OF_B254 49152
#define OF_MEMV 57344
#define OF_STG  91136
#define SMEM_T  103424

#define MMA_CHUNK(ACC)                                                              \
    {                                                                               \
        _Pragma("unroll")                                                           \
        for (int ks = 0; ks < 4; ks++) {                                            \
            int kb = ks * 32 + (lane >> 4) * 16;                                    \
            uint32_t af[2][4], bfr[2][4];                                           \
            _Pragma("unroll")                                                       \
            for (int mi = 0; mi < 2; mi++) {                                        \
                uint32_t byte = (uint32_t)((mw + mi * 16 + (lane & 15)) * 128 + kb);\
                byte ^= (byte >> 3) & 0x70;                                         \
                ldsm4(af[mi][0], af[mi][1], af[mi][2], af[mi][3], aB + byte);       \
            }                                                                       \
            _Pragma("unroll")                                                       \
            for (int jh = 0; jh < 2; jh++) {                                        \
                uint32_t byte = (uint32_t)((nw + jh * 16 + (lane & 15)) * 128 + kb);\
                byte ^= (byte >> 3) & 0x70;                                         \
                ldsm4(bfr[jh][0], bfr[jh][1], bfr[jh][2], bfr[jh][3], bB + byte);   \
            }                                                                       \
            _Pragma("unroll")                                                       \
            for (int mi = 0; mi < 2; mi++)                                          \
                _Pragma("unroll")                                                   \
                for (int j = 0; j < 4; j++)                                         \
                    mma_s8u8(ACC[mi][j], af[mi],                                    \
                             bfr[j >> 1][j & 1], bfr[j >> 1][(j & 1) + 2]);         \
        }                                                                           \
    }

template<int CSRC, int COUT, int EPI, int DUAL>
__global__ __launch_bounds__(256, 2) void gemm_i8(
    const int8_t* __restrict__ pack, const int8_t* __restrict__ XT,
    const float* __restrict__ sig,
    float* __restrict__ outF, int8_t* __restrict__ outS,
    const float* __restrict__ bias1,
    const float* __restrict__ scale, const float* __restrict__ shift,
    const float* __restrict__ scale2, const float* __restrict__ shift2,
    const float* __restrict__ res, float thr)
{
    extern __shared__ char smraw[];
    uint32_t smb0 = smem_u32(smraw);
    uint32_t smb = (smb0 + 1023u) & ~1023u;
    char* base = smraw + (smb - smb0);

    const int NKC = CSRC / 128;
    const int CHT = 3 * NKC;            // chunks per timestep
    const int G = T_ * CHT;
    const int n0g = blockIdx.x * 64;
    const int m0g = blockIdx.y * 128;
    const int b = blockIdx.z;
    const int tid = threadIdx.x;
    const int wid = tid >> 5, lane = tid & 31;
    const int mw = (wid >> 1) * 32, nw = (wid & 1) * 32;
    const int r = lane >> 2, qn = lane & 3;

    float psig[2][2];
#pragma unroll
    for (int mi = 0; mi < 2; mi++)
#pragma unroll
        for (int h = 0; h < 2; h++)
            psig[mi][h] = sig[m0g + mw + mi * 16 + h * 8 + r];

    int hi[2][4][4], lo[2][4][4];
#pragma unroll
    for (int mi = 0; mi < 2; mi++)
#pragma unroll
        for (int j = 0; j < 4; j++)
#pragma unroll
            for (int e = 0; e < 4; e++) { hi[mi][j][e] = 0; lo[mi][j][e] = 0; }

    float* memvp = (float*)(base + OF_MEMV);
    char* stg = base + OF_STG;

    auto issue = [&](int g) {
        int p = g / 3, tau = g - p * 3;
        int t = p / NKC, kc = p - t * NKC;
        const int8_t* asrc = pack + ((size_t)(blockIdx.y * 3 + tau) * NKC + kc) * 16384 + tid * 64;
        uint32_t adst = smb + (g & 1) * 16384 + tid * 64;
#pragma unroll
        for (int i = 0; i < 4; i++) cpasync16(adst + i * 16, asrc + i * 16);
        if (tau == 0) {
            int row = tid >> 2, q4 = tid & 3;
            const int8_t* bsrc = XT + ((size_t)((t * B_ + b) * NN + n0g + row)) * CSRC
                                    + kc * 128 + q4 * 32;
            uint32_t bb = smb + OF_B01 + (p & 1) * 8192;
#pragma unroll
            for (int i = 0; i < 2; i++) {
                uint32_t byte = (uint32_t)(row * 128 + q4 * 32 + i * 16);
                byte ^= (byte >> 3) & 0x70;
                cpasync16(bb + byte, bsrc + i * 16);
            }
        }
        cp_commit();
    };

    issue(0);
    for (int g = 0; g < G; g++) {
        cp_wait<0>();           // group g complete
        __syncthreads();        // orders prev-iteration reads before new writes
        if (g + 1 < G) issue(g + 1);

        int p = g / 3, tau = g - p * 3;
        uint32_t aB = smb + (g & 1) * 16384;
        uint32_t bB = (tau == 1) ? (smb + OF_B254) : (smb + OF_B01 + (p & 1) * 8192);

        if (tau == 0) { MMA_CHUNK(hi); }
        else          { MMA_CHUNK(lo); }

        if (tau == 0) {
            // build {0,254} variant: packed bytes are 0/1, *254 has no carries
            const uint4* s4 = (const uint4*)(base + OF_B01 + (p & 1) * 8192 + tid * 32);
            uint4* d4 = (uint4*)(base + OF_B254 + tid * 32);
#pragma unroll
            for (int i = 0; i < 2; i++) {
                uint4 v = s4[i];
                v.x *= 254u; v.y *= 254u; v.z *= 254u; v.w *= 254u;
                d4[i] = v;
            }
        }

        if (g % CHT == CHT - 1) {
            int t = g / CHT;
            const float* SCp = scale; const float* SHp = shift; int moff = m0g;
            if (DUAL && m0g >= 256) { SCp = scale2; SHp = shift2; moff = m0g - 256; }
#pragma unroll
            for (int mi = 0; mi < 2; mi++)
#pragma unroll
                for (int h = 0; h < 2; h++) {
                    int ml = mw + mi * 16 + h * 8 + r;
                    float sg = psig[mi][h];
                    float pb = bias1 ? bias1[m0g + ml] : 0.f;
                    float sc = SCp[moff + ml], sh = SHp[moff + ml];
#pragma unroll
                    for (int j = 0; j < 4; j++) {
#pragma unroll
                        for (int eo = 0; eo < 2; eo++) {
                            int e = h * 2 + eo;
                            int nl = nw + j * 8 + qn * 2 + eo;
                            float comb = (float)hi[mi][j][e]
                                       + (float)lo[mi][j][e] * (1.f / 64516.f);
                            float v = (comb * sg + pb) * sc + sh;
                            hi[mi][j][e] = 0; lo[mi][j][e] = 0;
                            if (EPI >= 1) {
                                size_t o = ((size_t)((t * B_ + b) * COUT) + m0g + ml) * NN
                                         + n0g + nl;
                                v += res[o];
                                outF[o] = v;
                            }
                            if (EPI != 1) {
                                float mv = (t == 0) ? 0.f : memvp[nl * 132 + ml];
                                float u = mv * 0.5f + v;
                                float sp = (u >= thr) ? 1.f : 0.f;
                                memvp[nl * 132 + ml] = u * (1.f - sp);
                                stg[nl * 160 + ml] = (char)(sp != 0.f);
                            }
                        }
                    }
                }
            if (EPI != 1) {
                __syncthreads();
                int row = tid >> 2, q4 = tid & 3;
                const uint4* s4 = (const uint4*)(stg + row * 160 + q4 * 32);
                uint4* d4 = (uint4*)(outS + ((size_t)((t * B_ + b) * NN + n0g + row)) * COUT
                                           + m0g + q4 * 32);
                d4[0] = s4[0]; d4[1] = s4[1];
            }
        }
    }
}

// ---------------- launch ----------------
extern "C" void kernel_launch(void* const* d_in, const int* in_sizes, int n_in,
                              void* d_out, int out_size) {
    const float* x         = (const float*)d_in[0];
    const float* q_w       = (const float*)d_in[1];
    const float* q_g       = (const float*)d_in[2];
    const float* q_b       = (const float*)d_in[3];
    const float* k_w       = (const float*)d_in[4];
    const float* k_g       = (const float*)d_in[5];
    const float* k_b       = (const float*)d_in[6];
    const float* proj_w    = (const float*)d_in[7];
    const float* proj_bias = (const float*)d_in[8];
    const float* proj_g    = (const float*)d_in[9];
    const float* proj_b2   = (const float*)d_in[10];
    const float* mem_alpha = (const float*)d_in[11];
    const float* w1        = (const float*)d_in[12];
    const float* b1        = (const float*)d_in[13];
    const float* bn1_g     = (const float*)d_in[14];
    const float* bn1_b     = (const float*)d_in[15];
    const float* w2        = (const float*)d_in[16];
    const float* b2        = (const float*)d_in[17];
    const float* bn2_g     = (const float*)d_in[18];
    const float* bn2_b     = (const float*)d_in[19];
    float* out = (float*)d_out;

    int8_t *xsT, *qkT, *y0T, *z0T, *z1T, *pqk, *pp, *pw1, *pw2;
    float *x1, *sqk, *spj, *sw1, *sw2;
    cudaGetSymbolAddress((void**)&xsT, g_xsT);
    cudaGetSymbolAddress((void**)&qkT, g_qkT);
    cudaGetSymbolAddress((void**)&y0T, g_y0T);
    cudaGetSymbolAddress((void**)&z0T, g_z0T);
    cudaGetSymbolAddress((void**)&z1T, g_z1T);
    cudaGetSymbolAddress((void**)&x1,  g_x1);
    cudaGetSymbolAddress((void**)&pqk, g_pqk);
    cudaGetSymbolAddress((void**)&pp,  g_pp);
    cudaGetSymbolAddress((void**)&pw1, g_pw1);
    cudaGetSymbolAddress((void**)&pw2, g_pw2);
    cudaGetSymbolAddress((void**)&sqk, g_sqk);
    cudaGetSymbolAddress((void**)&spj, g_spj);
    cudaGetSymbolAddress((void**)&sw1, g_sw1);
    cudaGetSymbolAddress((void**)&sw2, g_sw2);

    cudaFuncSetAttribute(gemm_i8<256, 512, 0, 1>,  cudaFuncAttributeMaxDynamicSharedMemorySize, SMEM_T);
    cudaFuncSetAttribute(gemm_i8<256, 256, 2, 0>,  cudaFuncAttributeMaxDynamicSharedMemorySize, SMEM_T);
    cudaFuncSetAttribute(gemm_i8<256, 1024, 0, 0>, cudaFuncAttributeMaxDynamicSharedMemorySize, SMEM_T);
    cudaFuncSetAttribute(gemm_i8<1024, 256, 1, 0>, cudaFuncAttributeMaxDynamicSharedMemorySize, SMEM_T);

    // 1-2. weight prep (2 launches)
    rowmax_all<<<256, 256>>>(q_w, k_w, proj_w, w1, w2);
    pack_all<<<2816, 256>>>(q_w, k_w, proj_w, w1, w2);

    dim3 lifg(32, 4, 16);
    dim3 gQK(16, 4, 16);
    dim3 gPJ(16, 2, 16);
    dim3 gW1(16, 8, 16);
    dim3 gW2(16, 2, 16);

    // 3. xsT = lifT(x)
    lif_t_kernel<<<lifg, 256>>>(x, xsT);
    // 4. merged q|k GEMM + bn + LIF -> qkT
    gemm_i8<256, 512, 0, 1><<<gQK, 256, SMEM_T>>>(pqk, xsT, sqk, nullptr, qkT,
        nullptr, q_g, q_b, k_g, k_b, nullptr, 1.f);
    // 5. attention -> y0T
    attn_kernel<<<(B_ * NN * 8) / 256, 256>>>(qkT, y0T, mem_alpha);
    // 6. proj: x1 = x + bn(proj@y0 + bias); z0T = lif(x1)
    gemm_i8<256, 256, 2, 0><<<gPJ, 256, SMEM_T>>>(pp, y0T, spj, x1, z0T,
        proj_bias, proj_g, proj_b2, nullptr, nullptr, x, 1.f);
    // 7. z1T = lif(bn1(w1@z0 + b1))
    gemm_i8<256, 1024, 0, 0><<<gW1, 256, SMEM_T>>>(pw1, z0T, sw1, nullptr, z1T,
        b1, bn1_g, bn1_b, nullptr, nullptr, nullptr, 1.f);
    // 8. out = x1 + bn2(w2@z1 + b2)
    gemm_i8<1024, 256, 1, 0><<<gW2, 256, SMEM_T>>>(pw2, z1T, sw2, out, nullptr,
        b2, bn2_g, bn2_b, nullptr, nullptr, x1, 0.f);
}

// round 8
// speedup vs baseline: 2.7620x; 2.4109x over previous
#include <cuda_runtime.h>
#include <cuda_fp16.h>
#include <cstdint>

#define T_ 4
#define B_ 16
#define NN 1024
#define C_ 256
#define CH_ 1024
#define SC (B_*C_*NN)       // 4194304 elems per t
#define SQK (B_*NN*512)
#define SCH (B_*CH_*NN)

// ---------------- scratch ----------------
__device__ __half g_xsT [(size_t)T_*SC];
__device__ __half g_qkT [(size_t)T_*SQK];   // [t][b][n][512]: 0-255 q, 256-511 k
__device__ __half g_y0T [(size_t)T_*SC];
__device__ __half g_z0T [(size_t)T_*SC];
__device__ __half g_z1T [(size_t)T_*SCH];
__device__ float  g_x1  [(size_t)T_*SC];
__device__ __half g_pqk [512*512];   // hi+lo
__device__ __half g_pp  [256*512];
__device__ __half g_pw1 [1024*512];
__device__ __half g_pw2 [256*1024];  // hi only

// ---------------- helpers ----------------
__device__ __forceinline__ uint32_t smem_u32(const void* p) {
    uint32_t a;
    asm("{ .reg .u64 t; cvta.to.shared.u64 t, %1; cvt.u32.u64 %0, t; }" : "=r"(a) : "l"(p));
    return a;
}
__device__ __forceinline__ void cpasync16(uint32_t dst, const void* src) {
    asm volatile("cp.async.cg.shared.global [%0], [%1], 16;" :: "r"(dst), "l"(src) : "memory");
}
__device__ __forceinline__ void cp_commit() { asm volatile("cp.async.commit_group;" ::: "memory"); }
template<int N> __device__ __forceinline__ void cp_wait() {
    asm volatile("cp.async.wait_group %0;" :: "n"(N) : "memory");
}
__device__ __forceinline__ void ldsm4(uint32_t& r0, uint32_t& r1, uint32_t& r2, uint32_t& r3, uint32_t addr) {
    asm volatile("ldmatrix.sync.aligned.m8n8.x4.shared.b16 {%0,%1,%2,%3}, [%4];"
                 : "=r"(r0), "=r"(r1), "=r"(r2), "=r"(r3) : "r"(addr));
}
__device__ __forceinline__ void mma16816(float* d, const uint32_t* a, uint32_t b0, uint32_t b1) {
    asm volatile("mma.sync.aligned.m16n8k16.row.col.f32.f16.f16.f32 "
                 "{%0,%1,%2,%3}, {%4,%5,%6,%7}, {%8,%9}, {%0,%1,%2,%3};"
                 : "+f"(d[0]), "+f"(d[1]), "+f"(d[2]), "+f"(d[3])
                 : "r"(a[0]), "r"(a[1]), "r"(a[2]), "r"(a[3]), "r"(b0), "r"(b1));
}

// packed-A element index: blocked 128(m) x 64(ke) fp16 tiles, SW128-swizzled.
__device__ __forceinline__ size_t blk_elem(int m, int ke, int nck) {
    int bm = m >> 7, rin = m & 127, kc = ke >> 6, c = ke & 63;
    uint32_t byte = (uint32_t)(rin * 128 + c * 2);
    byte ^= (byte >> 3) & 0x70;
    return ((size_t)bm * nck + kc) * 8192 + (byte >> 1);
}

// ---------------- weight packer: one launch ----------------
__device__ __forceinline__ void pack2(float w, __half* dst, int m, int k, int K, int nck) {
    __half hi = __float2half(w);
    float r = w - __half2float(hi);
    dst[blk_elem(m, k, nck)]     = hi;
    dst[blk_elem(m, K + k, nck)] = __float2half(r);
}
__global__ void pack_all(const float* __restrict__ qw, const float* __restrict__ kw,
                         const float* __restrict__ pw, const float* __restrict__ w1,
                         const float* __restrict__ w2) {
    int idx = blockIdx.x * 256 + threadIdx.x;
    if (idx < 131072) {                        // merged qk: M=512, K=256, nck=8
        int m = idx >> 8, k = idx & 255;
        float w = (m < 256) ? qw[m * 256 + k] : kw[(m - 256) * 256 + k];
        pack2(w, g_pqk, m, k, 256, 8);
    } else if (idx < 196608) {                 // proj 256x256
        int i = idx - 131072; int m = i >> 8, k = i & 255;
        pack2(pw[i], g_pp, m, k, 256, 8);
    } else if (idx < 458752) {                 // w1 1024x256
        int i = idx - 196608; int m = i >> 8, k = i & 255;
        pack2(w1[i], g_pw1, m, k, 256, 8);
    } else if (idx < 720896) {                 // w2 256x1024, HI ONLY, nck=16
        int i = idx - 458752; int m = i >> 10, k = i & 1023;
        g_pw2[blk_elem(m, k, 16)] = __float2half(w2[i]);
    }
}

// ---------------- LIF + transpose: fp32 [t,b,c,n] -> fp16 spikes [t,b,n,c] ----------------
__global__ void lif_t_kernel(const float* __restrict__ in, __half* __restrict__ out) {
    __shared__ __half st[4][32][72];
    int n0 = blockIdx.x * 32, c0 = blockIdx.y * 64, b = blockIdx.z;
    int nl = threadIdx.x & 31, cg = threadIdx.x >> 5;
#pragma unroll
    for (int pass = 0; pass < 8; pass++) {
        int cl = pass * 8 + cg;
        int c = c0 + cl;
        float mem = 0.f;
#pragma unroll
        for (int t = 0; t < T_; t++) {
            float v = mem * 0.5f + in[((size_t)(t * B_ + b) * C_ + c) * NN + n0 + nl];
            float sp = (v >= 1.0f) ? 1.f : 0.f;
            st[t][nl][cl] = __float2half(sp);
            mem = v * (1.f - sp);
        }
    }
    __syncthreads();
    int rr = threadIdx.x >> 1, hf = threadIdx.x & 1;
    int t = rr >> 5, n = rr & 31;
    size_t row = ((size_t)(t * B_ + b) * NN + n0 + n) * C_ + c0 + hf * 32;
    uint4* d = (uint4*)(out + row);
    const uint4* s = (const uint4*)(&st[t][n][hf * 32]);
#pragma unroll
    for (int i = 0; i < 4; i++) d[i] = s[i];
}

// ---------------- attention (merged fp16 qkT) ----------------
__global__ void attn_kernel(const __half* __restrict__ qk, __half* __restrict__ y,
                            const float* __restrict__ alpha_p) {
    int idx = blockIdx.x * 256 + threadIdx.x;
    int h = idx & 7;
    int n = (idx >> 3) & 1023;
    int b = idx >> 13;
    float alpha = *alpha_p;
    size_t baseq = ((size_t)(b * NN + n)) * 512 + h * 32;
    size_t basey = ((size_t)(b * NN + n)) * C_ + h * 32;

    float qs[T_];
#pragma unroll
    for (int t = 0; t < T_; t++) {
        const __half2* p = (const __half2*)(qk + (size_t)t * SQK + baseq);
        float s = 0.f;
#pragma unroll
        for (int i = 0; i < 16; i++) {
            float2 f = __half22float2(p[i]);
            s += f.x + f.y;
        }
        qs[t] = s;
    }
    float ms[T_];
    ms[0] = qs[0];
#pragma unroll
    for (int t = 1; t < T_; t++) ms[t] = alpha * ms[t - 1] + (1.f - alpha) * qs[t - 1];

    float mem = 0.f;
#pragma unroll
    for (int t = 0; t < T_; t++) {
        float v = mem * 0.5f + (ms[t] + qs[t]);
        float sp = (v >= 0.5f) ? 1.f : 0.f;
        mem = v * (1.f - sp);
        const uint4* kp = (const uint4*)(qk + (size_t)t * SQK + baseq + 256);
        uint4* yp = (uint4*)(y + (size_t)t * SC + basey);
        if (sp != 0.f) {
#pragma unroll
            for (int i = 0; i < 4; i++) yp[i] = kp[i];
        } else {
            uint4 z = {0, 0, 0, 0};
#pragma unroll
            for (int i = 0; i < 4; i++) yp[i] = z;
        }
    }
}

// ---------------- fp16 HMMA GEMM, fused epilogues ----------------
// CTA 128(M) x 128(N), BK=64 fp16; 8 warps 2m x 4n; warp 64x32.
// SPLIT=2: weights hi+lo (exact); SPLIT=1: hi only (w2 — no threshold after).
// EPI 0: bn affine + LIF -> fp16 spikes transposed [t,b,n,m]
// EPI 1: (acc+bias)*scale+shift + res -> fp32 [t,b,m,n]
// EPI 2: EPI1 write + LIF(result) -> spikes (proj: x1 and z0 fused)
#define SMEM_SP 101376
#define SMEM_NF 66560

template<int CSRC, int COUT, int EPI, int DUAL, int SPLIT>
__global__ __launch_bounds__(256) void gemm_mma(
    const __half* __restrict__ pack, const __half* __restrict__ XT,
    float* __restrict__ outF, __half* __restrict__ outS,
    const float* __restrict__ bias1,
    const float* __restrict__ scale, const float* __restrict__ shift,
    const float* __restrict__ scale2, const float* __restrict__ shift2,
    const float* __restrict__ res, float thr)
{
    extern __shared__ char smraw[];
    uint32_t smb0 = smem_u32(smraw);
    uint32_t smb = (smb0 + 1023u) & ~1023u;
    char* base = smraw + (smb - smb0);
    const uint32_t OF_A = 0, OF_B = 32768, OF_STG = 65536;

    const int NC = (SPLIT * CSRC) / 64;   // chunks per timestep
    const int G = T_ * NC;
    const int n0g = blockIdx.x * 128;
    const int m0g = blockIdx.y * 128;
    const int b = blockIdx.z;
    const int tid = threadIdx.x;
    const int wid = tid >> 5, lane = tid & 31;
    const int mw = (wid >> 2) * 64, nw = (wid & 3) * 32;
    const int r = lane >> 2, qn = lane & 3;

    const float* SCp = scale; const float* SHp = shift; int moff = m0g;
    if (DUAL && m0g >= 256) { SCp = scale2; SHp = shift2; moff = m0g - 256; }

    float pb[4][2], psc[4][2], psh[4][2];
#pragma unroll
    for (int mi = 0; mi < 4; mi++)
#pragma unroll
        for (int h = 0; h < 2; h++) {
            int ml = mw + mi * 16 + r + h * 8;
            pb[mi][h]  = bias1 ? bias1[m0g + ml] : 0.f;
            psc[mi][h] = SCp[moff + ml];
            psh[mi][h] = SHp[moff + ml];
        }

    float acc[4][4][4];
    float memv[4][4][4];
#pragma unroll
    for (int mi = 0; mi < 4; mi++)
#pragma unroll
        for (int j = 0; j < 4; j++)
#pragma unroll
            for (int e = 0; e < 4; e++) { acc[mi][j][e] = 0.f; memv[mi][j][e] = 0.f; }

    auto issue = [&](int g) {
        int t = g / NC, kc = g % NC;
        int buf = g & 1;
        const __half* asrc = pack + ((size_t)blockIdx.y * NC + kc) * 8192 + tid * 32;
        uint32_t adst = smb + OF_A + buf * 16384 + tid * 64;
#pragma unroll
        for (int i = 0; i < 4; i++) cpasync16(adst + i * 16, asrc + i * 8);
        int row = tid >> 1, hf = tid & 1;
        int kb = (kc * 64) % CSRC;
        const __half* bsrc = XT + ((size_t)((t * B_ + b) * NN + n0g + row)) * CSRC + kb + hf * 32;
        uint32_t bb = smb + OF_B + buf * 16384;
#pragma unroll
        for (int i = 0; i < 4; i++) {
            uint32_t byte = (uint32_t)(row * 128 + hf * 64 + i * 16);
            byte ^= ((byte >> 3) & 0x70);
            cpasync16(bb + byte, bsrc + i * 8);
        }
        cp_commit();
    };

    issue(0);
    for (int g = 0; g < G; g++) {
        if (g + 1 < G) { issue(g + 1); cp_wait<1>(); }
        else           { cp_wait<0>(); }
        __syncthreads();

        uint32_t aB = smb + OF_A + (g & 1) * 16384;
        uint32_t bB = smb + OF_B + (g & 1) * 16384;
#pragma unroll
        for (int ks = 0; ks < 4; ks++) {
            uint32_t af[4][4], bf[2][4];
#pragma unroll
            for (int mi = 0; mi < 4; mi++) {
                uint32_t byte = (uint32_t)((mw + mi * 16 + (lane & 15)) * 128 +
                                           (ks * 16 + (lane >> 4) * 8) * 2);
                byte ^= ((byte >> 3) & 0x70);
                ldsm4(af[mi][0], af[mi][1], af[mi][2], af[mi][3], aB + byte);
            }
#pragma unroll
            for (int j2 = 0; j2 < 2; j2++) {
                uint32_t byte = (uint32_t)((nw + j2 * 16 + (lane & 15)) * 128 +
                                           (ks * 16 + (lane >> 4) * 8) * 2);
                byte ^= ((byte >> 3) & 0x70);
                ldsm4(bf[j2][0], bf[j2][1], bf[j2][2], bf[j2][3], bB + byte);
            }
#pragma unroll
            for (int mi = 0; mi < 4; mi++)
#pragma unroll
                for (int j = 0; j < 4; j++)
                    mma16816(acc[mi][j], af[mi], bf[j >> 1][j & 1], bf[j >> 1][(j & 1) + 2]);
        }

        if ((g % NC) == NC - 1) {
            int t = g / NC;
#pragma unroll
            for (int mi = 0; mi < 4; mi++)
#pragma unroll
                for (int h = 0; h < 2; h++) {
                    int ml = mw + mi * 16 + r + h * 8;
#pragma unroll
                    for (int j = 0; j < 4; j++) {
#pragma unroll
                        for (int eo = 0; eo < 2; eo++) {
                            int e = h * 2 + eo;
                            int nl = nw + j * 8 + qn * 2 + eo;
                            float v = (acc[mi][j][e] + pb[mi][h]) * psc[mi][h] + psh[mi][h];
                            acc[mi][j][e] = 0.f;
                            if (EPI >= 1) {
                                size_t o = ((size_t)((t * B_ + b) * COUT) + m0g + ml) * NN
                                         + n0g + nl;
                                v += res[o];
                                outF[o] = v;
                            }
                            if (EPI != 1) {
                                float u = memv[mi][j][e] * 0.5f + v;
                                float sp = (u >= thr) ? 1.f : 0.f;
                                memv[mi][j][e] = u * (1.f - sp);
                                *(__half*)(base + OF_STG + nl * 272 + ml * 2) = __float2half(sp);
                            }
                        }
                    }
                }
            if (EPI != 1) {
                __syncthreads();
                int row = tid >> 1, hf = tid & 1;
                const uint4* s4 = (const uint4*)(base + OF_STG + row * 272 + hf * 128);
                uint4* d4 = (uint4*)(outS + ((size_t)((t * B_ + b) * NN + n0g + row)) * COUT
                                           + m0g + hf * 64);
#pragma unroll
                for (int i = 0; i < 8; i++) d4[i] = s4[i];
            }
        }
        __syncthreads();
    }
}

// ---------------- launch ----------------
extern "C" void kernel_launch(void* const* d_in, const int* in_sizes, int n_in,
                              void* d_out, int out_size) {
    const float* x         = (const float*)d_in[0];
    const float* q_w       = (const float*)d_in[1];
    const float* q_g       = (const float*)d_in[2];
    const float* q_b       = (const float*)d_in[3];
    const float* k_w       = (const float*)d_in[4];
    const float* k_g       = (const float*)d_in[5];
    const float* k_b       = (const float*)d_in[6];
    const float* proj_w    = (const float*)d_in[7];
    const float* proj_bias = (const float*)d_in[8];
    const float* proj_g    = (const float*)d_in[9];
    const float* proj_b2   = (const float*)d_in[10];
    const float* mem_alpha = (const float*)d_in[11];
    const float* w1        = (const float*)d_in[12];
    const float* b1        = (const float*)d_in[13];
    const float* bn1_g     = (const float*)d_in[14];
    const float* bn1_b     = (const float*)d_in[15];
    const float* w2        = (const float*)d_in[16];
    const float* b2        = (const float*)d_in[17];
    const float* bn2_g     = (const float*)d_in[18];
    const float* bn2_b     = (const float*)d_in[19];
    float* out = (float*)d_out;

    __half *xsT, *qkT, *y0T, *z0T, *z1T, *pqk, *pp, *pw1, *pw2;
    float* x1;
    cudaGetSymbolAddress((void**)&xsT, g_xsT);
    cudaGetSymbolAddress((void**)&qkT, g_qkT);
    cudaGetSymbolAddress((void**)&y0T, g_y0T);
    cudaGetSymbolAddress((void**)&z0T, g_z0T);
    cudaGetSymbolAddress((void**)&z1T, g_z1T);
    cudaGetSymbolAddress((void**)&x1,  g_x1);
    cudaGetSymbolAddress((void**)&pqk, g_pqk);
    cudaGetSymbolAddress((void**)&pp,  g_pp);
    cudaGetSymbolAddress((void**)&pw1, g_pw1);
    cudaGetSymbolAddress((void**)&pw2, g_pw2);

    cudaFuncSetAttribute(gemm_mma<256, 512, 0, 1, 2>,  cudaFuncAttributeMaxDynamicSharedMemorySize, SMEM_SP);
    cudaFuncSetAttribute(gemm_mma<256, 256, 2, 0, 2>,  cudaFuncAttributeMaxDynamicSharedMemorySize, SMEM_SP);
    cudaFuncSetAttribute(gemm_mma<256, 1024, 0, 0, 2>, cudaFuncAttributeMaxDynamicSharedMemorySize, SMEM_SP);
    cudaFuncSetAttribute(gemm_mma<1024, 256, 1, 0, 1>, cudaFuncAttributeMaxDynamicSharedMemorySize, SMEM_NF);

    // 1. pack all weights (hi/lo fp16; w2 hi-only)
    pack_all<<<2816, 256>>>(q_w, k_w, proj_w, w1, w2);

    dim3 lifg(32, 4, 16);
    dim3 gQK(8, 4, 16);
    dim3 gPJ(8, 2, 16);
    dim3 gW1(8, 8, 16);
    dim3 gW2(8, 2, 16);

    // 2. xsT = lifT(x)
    lif_t_kernel<<<lifg, 256>>>(x, xsT);
    // 3. merged q|k: GEMM + bn + LIF -> qkT
    gemm_mma<256, 512, 0, 1, 2><<<gQK, 256, SMEM_SP>>>(pqk, xsT, nullptr, qkT,
        nullptr, q_g, q_b, k_g, k_b, nullptr, 1.f);
    // 4. attention -> y0T
    attn_kernel<<<(B_ * NN * 8) / 256, 256>>>(qkT, y0T, mem_alpha);
    // 5. proj: x1 = x + bn(proj@y0 + bias); z0T = lif(x1)  (fused)
    gemm_mma<256, 256, 2, 0, 2><<<gPJ, 256, SMEM_SP>>>(pp, y0T, x1, z0T,
        proj_bias, proj_g, proj_b2, nullptr, nullptr, x, 1.f);
    // 6. z1T = lif(bn1(w1@z0 + b1))
    gemm_mma<256, 1024, 0, 0, 2><<<gW1, 256, SMEM_SP>>>(pw1, z0T, nullptr, z1T,
        b1, bn1_g, bn1_b, nullptr, nullptr, nullptr, 1.f);
    // 7. out = x1 + bn2(w2@z1 + b2)   (hi-only weights)
    gemm_mma<1024, 256, 1, 0, 1><<<gW2, 256, SMEM_NF>>>(pw2, z1T, out, nullptr,
        b2, bn2_g, bn2_b, nullptr, nullptr, x1, 0.f);
}

// round 9
// speedup vs baseline: 3.0244x; 1.0950x over previous
#include <cuda_runtime.h>
#include <cuda_fp16.h>
#include <cstdint>

#define T_ 4
#define B_ 16
#define NN 1024
#define C_ 256
#define CH_ 1024
#define SC (B_*C_*NN)       // 4194304 elems per t
#define SQK (B_*NN*512)
#define SCH (B_*CH_*NN)

// ---------------- scratch ----------------
__device__ __half g_xsT [(size_t)T_*SC];
__device__ __half g_qkT [(size_t)T_*SQK];   // [t][b][n][512]: 0-255 q, 256-511 k
__device__ __half g_y0T [(size_t)T_*SC];
__device__ __half g_z0T [(size_t)T_*SC];
__device__ __half g_z1T [(size_t)T_*SCH];
__device__ float  g_x1  [(size_t)T_*SC];
__device__ __half g_pqk [512*512];   // hi+lo
__device__ __half g_pp  [256*512];
__device__ __half g_pw1 [1024*512];
__device__ __half g_pw2 [256*1024];  // hi only

// ---------------- helpers ----------------
__device__ __forceinline__ uint32_t smem_u32(const void* p) {
    uint32_t a;
    asm("{ .reg .u64 t; cvta.to.shared.u64 t, %1; cvt.u32.u64 %0, t; }" : "=r"(a) : "l"(p));
    return a;
}
__device__ __forceinline__ void cpasync16(uint32_t dst, const void* src) {
    asm volatile("cp.async.cg.shared.global [%0], [%1], 16;" :: "r"(dst), "l"(src) : "memory");
}
__device__ __forceinline__ void cp_commit() { asm volatile("cp.async.commit_group;" ::: "memory"); }
template<int N> __device__ __forceinline__ void cp_wait() {
    asm volatile("cp.async.wait_group %0;" :: "n"(N) : "memory");
}
__device__ __forceinline__ void ldsm4(uint32_t& r0, uint32_t& r1, uint32_t& r2, uint32_t& r3, uint32_t addr) {
    asm volatile("ldmatrix.sync.aligned.m8n8.x4.shared.b16 {%0,%1,%2,%3}, [%4];"
                 : "=r"(r0), "=r"(r1), "=r"(r2), "=r"(r3) : "r"(addr));
}
__device__ __forceinline__ void mma16816(float* d, const uint32_t* a, uint32_t b0, uint32_t b1) {
    asm volatile("mma.sync.aligned.m16n8k16.row.col.f32.f16.f16.f32 "
                 "{%0,%1,%2,%3}, {%4,%5,%6,%7}, {%8,%9}, {%0,%1,%2,%3};"
                 : "+f"(d[0]), "+f"(d[1]), "+f"(d[2]), "+f"(d[3])
                 : "r"(a[0]), "r"(a[1]), "r"(a[2]), "r"(a[3]), "r"(b0), "r"(b1));
}

// packed-A element index: blocked 64(m) x 64(ke) fp16 tiles, SW128-swizzled.
__device__ __forceinline__ size_t blk_elem(int m, int ke, int nck) {
    int bm = m >> 6, rin = m & 63, kc = ke >> 6, c = ke & 63;
    uint32_t byte = (uint32_t)(rin * 128 + c * 2);
    byte ^= (byte >> 3) & 0x70;
    return ((size_t)bm * nck + kc) * 4096 + (byte >> 1);
}

// ---------------- weight packer: one launch ----------------
__device__ __forceinline__ void pack2(float w, __half* dst, int m, int k, int K, int nck) {
    __half hi = __float2half(w);
    float r = w - __half2float(hi);
    dst[blk_elem(m, k, nck)]     = hi;
    dst[blk_elem(m, K + k, nck)] = __float2half(r);
}
__global__ void pack_all(const float* __restrict__ qw, const float* __restrict__ kw,
                         const float* __restrict__ pw, const float* __restrict__ w1,
                         const float* __restrict__ w2) {
    int idx = blockIdx.x * 256 + threadIdx.x;
    if (idx < 131072) {                        // merged qk: M=512, K=256, nck=8
        int m = idx >> 8, k = idx & 255;
        float w = (m < 256) ? qw[m * 256 + k] : kw[(m - 256) * 256 + k];
        pack2(w, g_pqk, m, k, 256, 8);
    } else if (idx < 196608) {                 // proj 256x256
        int i = idx - 131072; int m = i >> 8, k = i & 255;
        pack2(pw[i], g_pp, m, k, 256, 8);
    } else if (idx < 458752) {                 // w1 1024x256
        int i = idx - 196608; int m = i >> 8, k = i & 255;
        pack2(w1[i], g_pw1, m, k, 256, 8);
    } else if (idx < 720896) {                 // w2 256x1024, HI ONLY, nck=16
        int i = idx - 458752; int m = i >> 10, k = i & 1023;
        g_pw2[blk_elem(m, k, 16)] = __float2half(w2[i]);
    }
}

// ---------------- LIF + transpose: fp32 [t,b,c,n] -> fp16 spikes [t,b,n,c] ----------------
__global__ void lif_t_kernel(const float* __restrict__ in, __half* __restrict__ out) {
    __shared__ __half st[4][32][72];
    int n0 = blockIdx.x * 32, c0 = blockIdx.y * 64, b = blockIdx.z;
    int nl = threadIdx.x & 31, cg = threadIdx.x >> 5;
#pragma unroll
    for (int pass = 0; pass < 8; pass++) {
        int cl = pass * 8 + cg;
        int c = c0 + cl;
        float mem = 0.f;
#pragma unroll
        for (int t = 0; t < T_; t++) {
            float v = mem * 0.5f + in[((size_t)(t * B_ + b) * C_ + c) * NN + n0 + nl];
            float sp = (v >= 1.0f) ? 1.f : 0.f;
            st[t][nl][cl] = __float2half(sp);
            mem = v * (1.f - sp);
        }
    }
    __syncthreads();
    int rr = threadIdx.x >> 1, hf = threadIdx.x & 1;
    int t = rr >> 5, n = rr & 31;
    size_t row = ((size_t)(t * B_ + b) * NN + n0 + n) * C_ + c0 + hf * 32;
    uint4* d = (uint4*)(out + row);
    const uint4* s = (const uint4*)(&st[t][n][hf * 32]);
#pragma unroll
    for (int i = 0; i < 4; i++) d[i] = s[i];
}

// ---------------- attention (merged fp16 qkT) ----------------
__global__ void attn_kernel(const __half* __restrict__ qk, __half* __restrict__ y,
                            const float* __restrict__ alpha_p) {
    int idx = blockIdx.x * 256 + threadIdx.x;
    int h = idx & 7;
    int n = (idx >> 3) & 1023;
    int b = idx >> 13;
    float alpha = *alpha_p;
    size_t baseq = ((size_t)(b * NN + n)) * 512 + h * 32;
    size_t basey = ((size_t)(b * NN + n)) * C_ + h * 32;

    float qs[T_];
#pragma unroll
    for (int t = 0; t < T_; t++) {
        const __half2* p = (const __half2*)(qk + (size_t)t * SQK + baseq);
        float s = 0.f;
#pragma unroll
        for (int i = 0; i < 16; i++) {
            float2 f = __half22float2(p[i]);
            s += f.x + f.y;
        }
        qs[t] = s;
    }
    float ms[T_];
    ms[0] = qs[0];
#pragma unroll
    for (int t = 1; t < T_; t++) ms[t] = alpha * ms[t - 1] + (1.f - alpha) * qs[t - 1];

    float mem = 0.f;
#pragma unroll
    for (int t = 0; t < T_; t++) {
        float v = mem * 0.5f + (ms[t] + qs[t]);
        float sp = (v >= 0.5f) ? 1.f : 0.f;
        mem = v * (1.f - sp);
        const uint4* kp = (const uint4*)(qk + (size_t)t * SQK + baseq + 256);
        uint4* yp = (uint4*)(y + (size_t)t * SC + basey);
        if (sp != 0.f) {
#pragma unroll
            for (int i = 0; i < 4; i++) yp[i] = kp[i];
        } else {
            uint4 z = {0, 0, 0, 0};
#pragma unroll
            for (int i = 0; i < 4; i++) yp[i] = z;
        }
    }
}

// ---------------- fp16 HMMA GEMM, fused epilogues ----------------
// CTA tile 64(M) x 128(N), BK=64; 8 warps 2m x 4n; warp 32x32; 2 CTAs/SM.
// SPLIT=2: weights hi+lo (exact); SPLIT=1: hi only (w2 — no threshold after).
// EPI 0: bn affine + LIF -> fp16 spikes transposed [t,b,n,m]
// EPI 1: (acc+bias)*scale+shift + res -> fp32 [t,b,m,n]
// EPI 2: EPI1 write + LIF(result) -> spikes (proj: x1 and z0 fused)
#define OF_A   0
#define OF_B   16384
#define OF_STG 49152
#define SMEM_SP 67584
#define SMEM_NF 49152

template<int CSRC, int COUT, int EPI, int DUAL, int SPLIT>
__global__ __launch_bounds__(256, 2) void gemm_mma(
    const __half* __restrict__ pack, const __half* __restrict__ XT,
    float* __restrict__ outF, __half* __restrict__ outS,
    const float* __restrict__ bias1,
    const float* __restrict__ scale, const float* __restrict__ shift,
    const float* __restrict__ scale2, const float* __restrict__ shift2,
    const float* __restrict__ res, float thr)
{
    extern __shared__ char smraw[];
    uint32_t smb0 = smem_u32(smraw);
    uint32_t smb = (smb0 + 1023u) & ~1023u;
    char* base = smraw + (smb - smb0);

    const int NC = (SPLIT * CSRC) / 64;   // chunks per timestep
    const int G = T_ * NC;
    const int n0g = blockIdx.x * 128;
    const int m0g = blockIdx.y * 64;
    const int b = blockIdx.z;
    const int tid = threadIdx.x;
    const int wid = tid >> 5, lane = tid & 31;
    const int mw = (wid >> 2) * 32, nw = (wid & 3) * 32;
    const int r = lane >> 2, qn = lane & 3;

    const float* SCp = scale; const float* SHp = shift; int moff = m0g;
    if (DUAL && m0g >= 256) { SCp = scale2; SHp = shift2; moff = m0g - 256; }

    float pb[2][2], psc[2][2], psh[2][2];
#pragma unroll
    for (int mi = 0; mi < 2; mi++)
#pragma unroll
        for (int h = 0; h < 2; h++) {
            int ml = mw + mi * 16 + r + h * 8;
            pb[mi][h]  = bias1 ? bias1[m0g + ml] : 0.f;
            psc[mi][h] = SCp[moff + ml];
            psh[mi][h] = SHp[moff + ml];
        }

    float acc[2][4][4];
    float memv[2][4][4];
#pragma unroll
    for (int mi = 0; mi < 2; mi++)
#pragma unroll
        for (int j = 0; j < 4; j++)
#pragma unroll
            for (int e = 0; e < 4; e++) { acc[mi][j][e] = 0.f; memv[mi][j][e] = 0.f; }

    auto issue = [&](int g) {
        int t = g / NC, kc = g % NC;
        int buf = g & 1;
        // A: 8KB pre-swizzled 64x64 block, linear copy (32B/thread)
        const __half* asrc = pack + ((size_t)blockIdx.y * NC + kc) * 4096 + tid * 16;
        uint32_t adst = smb + OF_A + buf * 8192 + tid * 32;
        cpasync16(adst, asrc);
        cpasync16(adst + 16, asrc + 8);
        // B: 128 rows x 128B, swizzled dst
        int row = tid >> 1, hf = tid & 1;
        int kb = (kc * 64) % CSRC;
        const __half* bsrc = XT + ((size_t)((t * B_ + b) * NN + n0g + row)) * CSRC + kb + hf * 32;
        uint32_t bb = smb + OF_B + buf * 16384;
#pragma unroll
        for (int i = 0; i < 4; i++) {
            uint32_t byte = (uint32_t)(row * 128 + hf * 64 + i * 16);
            byte ^= ((byte >> 3) & 0x70);
            cpasync16(bb + byte, bsrc + i * 8);
        }
        cp_commit();
    };

    issue(0);
    for (int g = 0; g < G; g++) {
        if (g + 1 < G) { issue(g + 1); cp_wait<1>(); }
        else           { cp_wait<0>(); }
        __syncthreads();

        uint32_t aB = smb + OF_A + (g & 1) * 8192;
        uint32_t bB = smb + OF_B + (g & 1) * 16384;
#pragma unroll
        for (int ks = 0; ks < 4; ks++) {
            uint32_t af[2][4], bf[2][4];
#pragma unroll
            for (int mi = 0; mi < 2; mi++) {
                uint32_t byte = (uint32_t)((mw + mi * 16 + (lane & 15)) * 128 +
                                           (ks * 16 + (lane >> 4) * 8) * 2);
                byte ^= ((byte >> 3) & 0x70);
                ldsm4(af[mi][0], af[mi][1], af[mi][2], af[mi][3], aB + byte);
            }
#pragma unroll
            for (int j2 = 0; j2 < 2; j2++) {
                uint32_t byte = (uint32_t)((nw + j2 * 16 + (lane & 15)) * 128 +
                                           (ks * 16 + (lane >> 4) * 8) * 2);
                byte ^= ((byte >> 3) & 0x70);
                ldsm4(bf[j2][0], bf[j2][1], bf[j2][2], bf[j2][3], bB + byte);
            }
#pragma unroll
            for (int mi = 0; mi < 2; mi++)
#pragma unroll
                for (int j = 0; j < 4; j++)
                    mma16816(acc[mi][j], af[mi], bf[j >> 1][j & 1], bf[j >> 1][(j & 1) + 2]);
        }

        if ((g % NC) == NC - 1) {
            int t = g / NC;
#pragma unroll
            for (int mi = 0; mi < 2; mi++)
#pragma unroll
                for (int h = 0; h < 2; h++) {
                    int ml = mw + mi * 16 + r + h * 8;
#pragma unroll
                    for (int j = 0; j < 4; j++) {
#pragma unroll
                        for (int eo = 0; eo < 2; eo++) {
                            int e = h * 2 + eo;
                            int nl = nw + j * 8 + qn * 2 + eo;
                            float v = (acc[mi][j][e] + pb[mi][h]) * psc[mi][h] + psh[mi][h];
                            acc[mi][j][e] = 0.f;
                            if (EPI >= 1) {
                                size_t o = ((size_t)((t * B_ + b) * COUT) + m0g + ml) * NN
                                         + n0g + nl;
                                v += res[o];
                                outF[o] = v;
                            }
                            if (EPI != 1) {
                                float u = memv[mi][j][e] * 0.5f + v;
                                float sp = (u >= thr) ? 1.f : 0.f;
                                memv[mi][j][e] = u * (1.f - sp);
                                *(__half*)(base + OF_STG + nl * 144 + ml * 2) = __float2half(sp);
                            }
                        }
                    }
                }
            if (EPI != 1) {
                __syncthreads();
                int row = tid >> 1, hf = tid & 1;
                const uint4* s4 = (const uint4*)(base + OF_STG + row * 144 + hf * 64);
                uint4* d4 = (uint4*)(outS + ((size_t)((t * B_ + b) * NN + n0g + row)) * COUT
                                           + m0g + hf * 32);
#pragma unroll
                for (int i = 0; i < 4; i++) d4[i] = s4[i];
            }
        }
        __syncthreads();
    }
}

// ---------------- launch ----------------
extern "C" void kernel_launch(void* const* d_in, const int* in_sizes, int n_in,
                              void* d_out, int out_size) {
    const float* x         = (const float*)d_in[0];
    const float* q_w       = (const float*)d_in[1];
    const float* q_g       = (const float*)d_in[2];
    const float* q_b       = (const float*)d_in[3];
    const float* k_w       = (const float*)d_in[4];
    const float* k_g       = (const float*)d_in[5];
    const float* k_b       = (const float*)d_in[6];
    const float* proj_w    = (const float*)d_in[7];
    const float* proj_bias = (const float*)d_in[8];
    const float* proj_g    = (const float*)d_in[9];
    const float* proj_b2   = (const float*)d_in[10];
    const float* mem_alpha = (const float*)d_in[11];
    const float* w1        = (const float*)d_in[12];
    const float* b1        = (const float*)d_in[13];
    const float* bn1_g     = (const float*)d_in[14];
    const float* bn1_b     = (const float*)d_in[15];
    const float* w2        = (const float*)d_in[16];
    const float* b2        = (const float*)d_in[17];
    const float* bn2_g     = (const float*)d_in[18];
    const float* bn2_b     = (const float*)d_in[19];
    float* out = (float*)d_out;

    __half *xsT, *qkT, *y0T, *z0T, *z1T, *pqk, *pp, *pw1, *pw2;
    float* x1;
    cudaGetSymbolAddress((void**)&xsT, g_xsT);
    cudaGetSymbolAddress((void**)&qkT, g_qkT);
    cudaGetSymbolAddress((void**)&y0T, g_y0T);
    cudaGetSymbolAddress((void**)&z0T, g_z0T);
    cudaGetSymbolAddress((void**)&z1T, g_z1T);
    cudaGetSymbolAddress((void**)&x1,  g_x1);
    cudaGetSymbolAddress((void**)&pqk, g_pqk);
    cudaGetSymbolAddress((void**)&pp,  g_pp);
    cudaGetSymbolAddress((void**)&pw1, g_pw1);
    cudaGetSymbolAddress((void**)&pw2, g_pw2);

    cudaFuncSetAttribute(gemm_mma<256, 512, 0, 1, 2>,  cudaFuncAttributeMaxDynamicSharedMemorySize, SMEM_SP);
    cudaFuncSetAttribute(gemm_mma<256, 256, 2, 0, 2>,  cudaFuncAttributeMaxDynamicSharedMemorySize, SMEM_SP);
    cudaFuncSetAttribute(gemm_mma<256, 1024, 0, 0, 2>, cudaFuncAttributeMaxDynamicSharedMemorySize, SMEM_SP);
    cudaFuncSetAttribute(gemm_mma<1024, 256, 1, 0, 1>, cudaFuncAttributeMaxDynamicSharedMemorySize, SMEM_NF);

    // 1. pack all weights (hi/lo fp16; w2 hi-only), 64-row blocks
    pack_all<<<2816, 256>>>(q_w, k_w, proj_w, w1, w2);

    dim3 lifg(32, 4, 16);
    dim3 gQK(8, 8, 16);
    dim3 gPJ(8, 4, 16);
    dim3 gW1(8, 16, 16);
    dim3 gW2(8, 4, 16);

    // 2. xsT = lifT(x)
    lif_t_kernel<<<lifg, 256>>>(x, xsT);
    // 3. merged q|k: GEMM + bn + LIF -> qkT
    gemm_mma<256, 512, 0, 1, 2><<<gQK, 256, SMEM_SP>>>(pqk, xsT, nullptr, qkT,
        nullptr, q_g, q_b, k_g, k_b, nullptr, 1.f);
    // 4. attention -> y0T
    attn_kernel<<<(B_ * NN * 8) / 256, 256>>>(qkT, y0T, mem_alpha);
    // 5. proj: x1 = x + bn(proj@y0 + bias); z0T = lif(x1)  (fused)
    gemm_mma<256, 256, 2, 0, 2><<<gPJ, 256, SMEM_SP>>>(pp, y0T, x1, z0T,
        proj_bias, proj_g, proj_b2, nullptr, nullptr, x, 1.f);
    // 6. z1T = lif(bn1(w1@z0 + b1))
    gemm_mma<256, 1024, 0, 0, 2><<<gW1, 256, SMEM_SP>>>(pw1, z0T, nullptr, z1T,
        b1, bn1_g, bn1_b, nullptr, nullptr, nullptr, 1.f);
    // 7. out = x1 + bn2(w2@z1 + b2)   (hi-only weights)
    gemm_mma<1024, 256, 1, 0, 1><<<gW2, 256, SMEM_NF>>>(pw2, z1T, out, nullptr,
        b2, bn2_g, bn2_b, nullptr, nullptr, x1, 0.f);
}